// round 4
// baseline (speedup 1.0000x reference)
#include <cuda_runtime.h>
#include <cstdint>

#define N_SEG 50000
#define D_FEAT 128
#define OUT_F 128
#define KDIM 256

// Scratch (allocation-free rule: __device__ globals)
__device__ float g_pooled[(size_t)N_SEG * KDIM];   // [N, 256] = 51.2 MB
__device__ int   g_starts[N_SEG + 1];
__device__ int   g_is64;

// Packed fp32x2 helpers (sm_100+ PTX)
#define PACK2(out, lo, hi) \
    asm("mov.b64 %0, {%1, %2};" : "=l"(out) : "f"(lo), "f"(hi))
#define UNPACK2(lo, hi, in) \
    asm("mov.b64 {%0, %1}, %2;" : "=f"(lo), "=f"(hi) : "l"(in))
#define FMA2(d, a, bb) \
    asm("fma.rn.f32x2 %0, %1, %2, %0;" : "+l"(d) : "l"(a), "l"(bb))

// ---------------------------------------------------------------------------
// Kernel -1: detect whether ids are int64 or int32 (odd int32 words all zero
// in the middle of a sorted int64 array with values < 2^31).
// ---------------------------------------------------------------------------
__global__ void detect_kernel(const int* __restrict__ ids32, int M) {
    int base = (M / 2) & ~1;
    int nonzero = 0;
    for (int i = 1; i <= 63; i += 2) {
        if (base + i < M) nonzero |= ids32[base + i];
    }
    g_is64 = (nonzero == 0) ? 1 : 0;
}

// ---------------------------------------------------------------------------
// Kernel 0: segment boundaries from sorted ids (dtype-agnostic via g_is64).
// ---------------------------------------------------------------------------
__global__ void bounds_kernel(const int* __restrict__ ids32, int M, int Nseg) {
    int m = blockIdx.x * blockDim.x + threadIdx.x;
    if (m >= M) return;
    const long long* ids64 = (const long long*)ids32;
    int is64 = g_is64;

    long long id = is64 ? ids64[m] : (long long)ids32[m];
    if (id < 0 || id >= Nseg) return;
    if (m == 0) {
        g_starts[id] = 0;
    } else {
        long long prev = is64 ? ids64[m - 1] : (long long)ids32[m - 1];
        if (prev != id) g_starts[id] = m;
    }
    if (m == M - 1) g_starts[Nseg] = M;
}

// ---------------------------------------------------------------------------
// Kernel 1: segmented max + mean. One block (128 threads) per segment;
// thread t owns feature column t -> coalesced 512B row reads.
// ---------------------------------------------------------------------------
__global__ __launch_bounds__(128) void pool_kernel(const float* __restrict__ lane,
                                                   int M) {
    int seg = blockIdx.x;
    int col = threadIdx.x;
    int s = g_starts[seg];
    int e = g_starts[seg + 1];
    if (s < 0) s = 0;
    if (e > M) e = M;
    int n = e - s;
    if (n <= 0) {
        float* dst0 = g_pooled + (size_t)seg * KDIM;
        dst0[col] = 0.f; dst0[D_FEAT + col] = 0.f;
        return;
    }

    const float* p = lane + (size_t)s * D_FEAT + col;
    float mx = -__int_as_float(0x7f800000);
    float sm = 0.f;

    int r = 0;
    for (; r + 4 <= n; r += 4) {
        float a0 = p[(size_t)(r + 0) * D_FEAT];
        float a1 = p[(size_t)(r + 1) * D_FEAT];
        float a2 = p[(size_t)(r + 2) * D_FEAT];
        float a3 = p[(size_t)(r + 3) * D_FEAT];
        mx = fmaxf(mx, fmaxf(fmaxf(a0, a1), fmaxf(a2, a3)));
        sm += (a0 + a1) + (a2 + a3);
    }
    for (; r < n; r++) {
        float a = p[(size_t)r * D_FEAT];
        mx = fmaxf(mx, a);
        sm += a;
    }

    float* dst = g_pooled + (size_t)seg * KDIM;
    dst[col]          = mx;
    dst[D_FEAT + col] = sm / (float)n;
}

// ---------------------------------------------------------------------------
// Kernel 2: out = relu(pooled @ W^T + b) using packed fma.rn.f32x2.
// Tile 64 rows x 128 cols, 256 threads, 4x8 micro-tile (4x4 f32x2 acc).
// Register-prefetch double buffering over K-chunks of 32.
// ---------------------------------------------------------------------------
#define TM 64
#define KC 32
#define NCHUNK (KDIM / KC)     // 8

__global__ __launch_bounds__(256, 2) void gemm_kernel(const float* __restrict__ W,
                                                      const float* __restrict__ bias,
                                                      float* __restrict__ out,
                                                      int Nrows) {
    __shared__ float As[KC][TM + 4];       // [k][row], +4 pad (16B-aligned rows)
    __shared__ float Ws[KC][OUT_F + 4];    // [k][o]

    int tid = threadIdx.x;
    int row0 = blockIdx.x * TM;
    int tx = tid & 15;    // 16 col groups of 8
    int ty = tid >> 4;    // 16 row groups of 4

    unsigned long long acc2[4][4];
    #pragma unroll
    for (int i = 0; i < 4; i++)
        #pragma unroll
        for (int p = 0; p < 4; p++) acc2[i][p] = 0ull;

    float ra[8];    // A prefetch: 64*32/256 = 8 per thread
    float rw[16];   // W prefetch: 128*32/256 = 16 per thread

    // Prefetch chunk 0
    #pragma unroll
    for (int i = 0; i < 8; i++) {
        int idx = tid + i * 256;
        int rr = idx >> 5, kk = idx & 31;
        int gr = row0 + rr;
        ra[i] = (gr < Nrows) ? g_pooled[(size_t)gr * KDIM + kk] : 0.f;
    }
    #pragma unroll
    for (int i = 0; i < 16; i++) {
        int idx = tid + i * 256;
        int oo = idx >> 5, kk = idx & 31;
        rw[i] = W[(size_t)oo * KDIM + kk];
    }

    for (int c = 0; c < NCHUNK; c++) {
        // Store prefetched chunk to smem
        #pragma unroll
        for (int i = 0; i < 8; i++) {
            int idx = tid + i * 256;
            int rr = idx >> 5, kk = idx & 31;
            As[kk][rr] = ra[i];
        }
        #pragma unroll
        for (int i = 0; i < 16; i++) {
            int idx = tid + i * 256;
            int oo = idx >> 5, kk = idx & 31;
            Ws[kk][oo] = rw[i];
        }
        __syncthreads();

        // Prefetch next chunk (global loads overlap with compute below)
        if (c + 1 < NCHUNK) {
            int kc = (c + 1) * KC;
            #pragma unroll
            for (int i = 0; i < 8; i++) {
                int idx = tid + i * 256;
                int rr = idx >> 5, kk = idx & 31;
                int gr = row0 + rr;
                ra[i] = (gr < Nrows) ? g_pooled[(size_t)gr * KDIM + kc + kk] : 0.f;
            }
            #pragma unroll
            for (int i = 0; i < 16; i++) {
                int idx = tid + i * 256;
                int oo = idx >> 5, kk = idx & 31;
                rw[i] = W[(size_t)oo * KDIM + kc + kk];
            }
        }

        // Compute current chunk from smem
        #pragma unroll
        for (int k = 0; k < KC; k++) {
            float4 av = *(const float4*)&As[k][ty * 4];
            float4 w0 = *(const float4*)&Ws[k][tx * 8];
            float4 w1 = *(const float4*)&Ws[k][tx * 8 + 4];

            unsigned long long wp[4], ap[4];
            PACK2(wp[0], w0.x, w0.y);
            PACK2(wp[1], w0.z, w0.w);
            PACK2(wp[2], w1.x, w1.y);
            PACK2(wp[3], w1.z, w1.w);
            PACK2(ap[0], av.x, av.x);
            PACK2(ap[1], av.y, av.y);
            PACK2(ap[2], av.z, av.z);
            PACK2(ap[3], av.w, av.w);

            #pragma unroll
            for (int i = 0; i < 4; i++)
                #pragma unroll
                for (int p = 0; p < 4; p++)
                    FMA2(acc2[i][p], ap[i], wp[p]);
        }
        __syncthreads();
    }

    // Epilogue: bias + relu, vectorized store
    float bj[8];
    #pragma unroll
    for (int j = 0; j < 8; j++) bj[j] = bias[tx * 8 + j];

    #pragma unroll
    for (int i = 0; i < 4; i++) {
        int gr = row0 + ty * 4 + i;
        if (gr >= Nrows) break;
        float v[8];
        #pragma unroll
        for (int p = 0; p < 4; p++) UNPACK2(v[2 * p], v[2 * p + 1], acc2[i][p]);
        float4 o0, o1;
        o0.x = fmaxf(v[0] + bj[0], 0.f);
        o0.y = fmaxf(v[1] + bj[1], 0.f);
        o0.z = fmaxf(v[2] + bj[2], 0.f);
        o0.w = fmaxf(v[3] + bj[3], 0.f);
        o1.x = fmaxf(v[4] + bj[4], 0.f);
        o1.y = fmaxf(v[5] + bj[5], 0.f);
        o1.z = fmaxf(v[6] + bj[6], 0.f);
        o1.w = fmaxf(v[7] + bj[7], 0.f);
        *(float4*)&out[(size_t)gr * OUT_F + tx * 8]     = o0;
        *(float4*)&out[(size_t)gr * OUT_F + tx * 8 + 4] = o1;
    }
}

extern "C" void kernel_launch(void* const* d_in, const int* in_sizes, int n_in,
                              void* d_out, int out_size) {
    const float* lane = nullptr;
    const int*   ids  = nullptr;
    const float* W    = nullptr;
    const float* bb   = nullptr;
    int M = 800000, Nseg = 50000;

    for (int i = 0; i < n_in; i++) {
        int sz = in_sizes[i];
        if (sz == 102400000)      lane = (const float*)d_in[i];
        else if (sz == 800000)  { ids  = (const int*)d_in[i]; M = sz; }
        else if (sz == 32768)     W    = (const float*)d_in[i];
        else if (sz == 128)       bb   = (const float*)d_in[i];
        else if (sz == 6400000)   Nseg = sz / D_FEAT;
    }
    if (!lane) lane = (const float*)d_in[1];
    if (!ids)  ids  = (const int*)d_in[2];
    if (!W)    W    = (const float*)d_in[3];
    if (!bb)   bb   = (const float*)d_in[4];

    float* out = (float*)d_out;

    detect_kernel<<<1, 1>>>(ids, M);
    bounds_kernel<<<(M + 255) / 256, 256>>>(ids, M, Nseg);
    pool_kernel<<<Nseg, 128>>>(lane, M);
    gemm_kernel<<<(Nseg + TM - 1) / TM, 256>>>(W, bb, out, Nseg);
}

// round 5
// speedup vs baseline: 1.3448x; 1.3448x over previous
#include <cuda_runtime.h>
#include <cstdint>

#define N_SEG 50000
#define D_FEAT 128
#define OUT_F 128
#define KDIM 256

// Scratch (allocation-free rule: __device__ globals)
__device__ float g_pooled[(size_t)N_SEG * KDIM];   // [N, 256] = 51.2 MB
__device__ int   g_starts[N_SEG + 1];
__device__ int   g_is64;

// ---------------------------------------------------------------------------
// Kernel -1: detect whether ids are int64 or int32 (odd int32 words all zero
// in the middle of a sorted int64 array with values < 2^31).
// ---------------------------------------------------------------------------
__global__ void detect_kernel(const int* __restrict__ ids32, int M) {
    int base = (M / 2) & ~1;
    int nonzero = 0;
    for (int i = 1; i <= 63; i += 2) {
        if (base + i < M) nonzero |= ids32[base + i];
    }
    g_is64 = (nonzero == 0) ? 1 : 0;
}

// ---------------------------------------------------------------------------
// Kernel 0: segment boundaries from sorted ids (dtype-agnostic via g_is64).
// ---------------------------------------------------------------------------
__global__ void bounds_kernel(const int* __restrict__ ids32, int M, int Nseg) {
    int m = blockIdx.x * blockDim.x + threadIdx.x;
    if (m >= M) return;
    const long long* ids64 = (const long long*)ids32;
    int is64 = g_is64;

    long long id = is64 ? ids64[m] : (long long)ids32[m];
    if (id < 0 || id >= Nseg) return;
    if (m == 0) {
        g_starts[id] = 0;
    } else {
        long long prev = is64 ? ids64[m - 1] : (long long)ids32[m - 1];
        if (prev != id) g_starts[id] = m;
    }
    if (m == M - 1) g_starts[Nseg] = M;
}

// ---------------------------------------------------------------------------
// Kernel 1: segmented max + mean. One block (128 threads) per segment;
// thread t owns feature column t -> coalesced 512B row reads.
// ---------------------------------------------------------------------------
__global__ __launch_bounds__(128) void pool_kernel(const float* __restrict__ lane,
                                                   int M) {
    int seg = blockIdx.x;
    int col = threadIdx.x;
    int s = g_starts[seg];
    int e = g_starts[seg + 1];
    if (s < 0) s = 0;
    if (e > M) e = M;
    int n = e - s;
    if (n <= 0) {
        float* dst0 = g_pooled + (size_t)seg * KDIM;
        dst0[col] = 0.f; dst0[D_FEAT + col] = 0.f;
        return;
    }

    const float* p = lane + (size_t)s * D_FEAT + col;
    float mx = -__int_as_float(0x7f800000);
    float sm = 0.f;

    int r = 0;
    for (; r + 4 <= n; r += 4) {
        float a0 = p[(size_t)(r + 0) * D_FEAT];
        float a1 = p[(size_t)(r + 1) * D_FEAT];
        float a2 = p[(size_t)(r + 2) * D_FEAT];
        float a3 = p[(size_t)(r + 3) * D_FEAT];
        mx = fmaxf(mx, fmaxf(fmaxf(a0, a1), fmaxf(a2, a3)));
        sm += (a0 + a1) + (a2 + a3);
    }
    for (; r < n; r++) {
        float a = p[(size_t)r * D_FEAT];
        mx = fmaxf(mx, a);
        sm += a;
    }

    float* dst = g_pooled + (size_t)seg * KDIM;
    dst[col]          = mx;
    dst[D_FEAT + col] = sm / (float)n;
}

// ---------------------------------------------------------------------------
// Kernel 2: out = relu(pooled @ W^T + b) on the TENSOR pipe.
// Split-tf32 (hi+lo) 3-MMA scheme for fp32-class accuracy.
// Block: 256 thr (8 warps, 2x4), tile 64x128, K-chunks of 32.
// ---------------------------------------------------------------------------
#define TM 64
#define KC 32

__device__ __forceinline__ void split_tf32(float x, uint32_t& hi, uint32_t& lo) {
    asm("cvt.rna.tf32.f32 %0, %1;" : "=r"(hi) : "f"(x));
    float l = x - __uint_as_float(hi);
    asm("cvt.rna.tf32.f32 %0, %1;" : "=r"(lo) : "f"(l));
}

__device__ __forceinline__ void mma_tf32(float* c, const uint32_t* a, const uint32_t* b) {
    asm volatile(
        "mma.sync.aligned.m16n8k8.row.col.f32.tf32.tf32.f32 "
        "{%0,%1,%2,%3}, {%4,%5,%6,%7}, {%8,%9}, {%0,%1,%2,%3};"
        : "+f"(c[0]), "+f"(c[1]), "+f"(c[2]), "+f"(c[3])
        : "r"(a[0]), "r"(a[1]), "r"(a[2]), "r"(a[3]), "r"(b[0]), "r"(b[1]));
}

__global__ __launch_bounds__(256, 2) void gemm_kernel(const float* __restrict__ W,
                                                      const float* __restrict__ bias,
                                                      float* __restrict__ out,
                                                      int Nrows) {
    // Stride 36: addr%32 = (4*row + col)%32 -> conflict-free fragment loads
    __shared__ float As[TM][36];      // [row][k]
    __shared__ float Ws[OUT_F][36];   // [n][k]

    int tid  = threadIdx.x;
    int lane = tid & 31;
    int wid  = tid >> 5;
    int warp_m = wid & 1;    // 2 warps in m
    int warp_n = wid >> 1;   // 4 warps in n
    int lr = lane >> 2;      // 0..7
    int lc = lane & 3;       // 0..3
    int row0 = blockIdx.x * TM;

    float acc[2][4][4];      // [m-atom][n-atom][c-regs]
    #pragma unroll
    for (int i = 0; i < 2; i++)
        #pragma unroll
        for (int j = 0; j < 4; j++)
            #pragma unroll
            for (int r = 0; r < 4; r++) acc[i][j][r] = 0.f;

    float ra[8];    // A prefetch: 64*32/256 = 8 per thread
    float rw[16];   // W prefetch: 128*32/256 = 16 per thread

    // Prefetch chunk 0
    #pragma unroll
    for (int i = 0; i < 8; i++) {
        int idx = tid + i * 256;
        int rr = idx >> 5, kk = idx & 31;
        int gr = row0 + rr;
        ra[i] = (gr < Nrows) ? g_pooled[(size_t)gr * KDIM + kk] : 0.f;
    }
    #pragma unroll
    for (int i = 0; i < 16; i++) {
        int idx = tid + i * 256;
        int oo = idx >> 5, kk = idx & 31;
        rw[i] = W[(size_t)oo * KDIM + kk];
    }

    for (int c = 0; c < KDIM / KC; c++) {
        #pragma unroll
        for (int i = 0; i < 8; i++) {
            int idx = tid + i * 256;
            As[idx >> 5][idx & 31] = ra[i];
        }
        #pragma unroll
        for (int i = 0; i < 16; i++) {
            int idx = tid + i * 256;
            Ws[idx >> 5][idx & 31] = rw[i];
        }
        __syncthreads();

        // Prefetch next chunk (overlaps with MMA below)
        if (c + 1 < KDIM / KC) {
            int kc = (c + 1) * KC;
            #pragma unroll
            for (int i = 0; i < 8; i++) {
                int idx = tid + i * 256;
                int rr = idx >> 5, kk = idx & 31;
                int gr = row0 + rr;
                ra[i] = (gr < Nrows) ? g_pooled[(size_t)gr * KDIM + kc + kk] : 0.f;
            }
            #pragma unroll
            for (int i = 0; i < 16; i++) {
                int idx = tid + i * 256;
                int oo = idx >> 5, kk = idx & 31;
                rw[i] = W[(size_t)oo * KDIM + kc + kk];
            }
        }

        // 4 k-atoms of 8
        #pragma unroll
        for (int ka = 0; ka < 4; ka++) {
            int k8 = ka * 8;

            uint32_t ah[2][4], al[2][4];
            #pragma unroll
            for (int am = 0; am < 2; am++) {
                int br = warp_m * 32 + am * 16;
                float f0 = As[br + lr    ][k8 + lc    ];
                float f1 = As[br + lr + 8][k8 + lc    ];
                float f2 = As[br + lr    ][k8 + lc + 4];
                float f3 = As[br + lr + 8][k8 + lc + 4];
                split_tf32(f0, ah[am][0], al[am][0]);
                split_tf32(f1, ah[am][1], al[am][1]);
                split_tf32(f2, ah[am][2], al[am][2]);
                split_tf32(f3, ah[am][3], al[am][3]);
            }
            uint32_t bh[4][2], bl[4][2];
            #pragma unroll
            for (int an = 0; an < 4; an++) {
                int bn = warp_n * 32 + an * 8 + lr;
                float f0 = Ws[bn][k8 + lc    ];
                float f1 = Ws[bn][k8 + lc + 4];
                split_tf32(f0, bh[an][0], bl[an][0]);
                split_tf32(f1, bh[an][1], bl[an][1]);
            }

            #pragma unroll
            for (int am = 0; am < 2; am++)
                #pragma unroll
                for (int an = 0; an < 4; an++) {
                    mma_tf32(acc[am][an], ah[am], bl[an]);  // hi*lo
                    mma_tf32(acc[am][an], al[am], bh[an]);  // lo*hi
                    mma_tf32(acc[am][an], ah[am], bh[an]);  // hi*hi
                }
        }
        __syncthreads();
    }

    // Epilogue: bias + relu
    #pragma unroll
    for (int an = 0; an < 4; an++) {
        int gn = warp_n * 32 + an * 8 + lc * 2;
        float b0 = bias[gn], b1 = bias[gn + 1];
        #pragma unroll
        for (int am = 0; am < 2; am++) {
            int gm0 = row0 + warp_m * 32 + am * 16 + lr;
            int gm1 = gm0 + 8;
            if (gm0 < Nrows) {
                float2 v;
                v.x = fmaxf(acc[am][an][0] + b0, 0.f);
                v.y = fmaxf(acc[am][an][1] + b1, 0.f);
                *(float2*)&out[(size_t)gm0 * OUT_F + gn] = v;
            }
            if (gm1 < Nrows) {
                float2 v;
                v.x = fmaxf(acc[am][an][2] + b0, 0.f);
                v.y = fmaxf(acc[am][an][3] + b1, 0.f);
                *(float2*)&out[(size_t)gm1 * OUT_F + gn] = v;
            }
        }
    }
}

extern "C" void kernel_launch(void* const* d_in, const int* in_sizes, int n_in,
                              void* d_out, int out_size) {
    const float* lane = nullptr;
    const int*   ids  = nullptr;
    const float* W    = nullptr;
    const float* bb   = nullptr;
    int M = 800000, Nseg = 50000;

    for (int i = 0; i < n_in; i++) {
        int sz = in_sizes[i];
        if (sz == 102400000)      lane = (const float*)d_in[i];
        else if (sz == 800000)  { ids  = (const int*)d_in[i]; M = sz; }
        else if (sz == 32768)     W    = (const float*)d_in[i];
        else if (sz == 128)       bb   = (const float*)d_in[i];
        else if (sz == 6400000)   Nseg = sz / D_FEAT;
    }
    if (!lane) lane = (const float*)d_in[1];
    if (!ids)  ids  = (const int*)d_in[2];
    if (!W)    W    = (const float*)d_in[3];
    if (!bb)   bb   = (const float*)d_in[4];

    float* out = (float*)d_out;

    detect_kernel<<<1, 1>>>(ids, M);
    bounds_kernel<<<(M + 255) / 256, 256>>>(ids, M, Nseg);
    pool_kernel<<<Nseg, 128>>>(lane, M);
    gemm_kernel<<<(Nseg + TM - 1) / TM, 256>>>(W, bb, out, Nseg);
}

// round 6
// speedup vs baseline: 1.4404x; 1.0710x over previous
#include <cuda_runtime.h>
#include <cstdint>

#define N_SEG 50000
#define D_FEAT 128
#define OUT_F 128
#define KDIM 256

// Scratch (allocation-free rule: __device__ globals)
__device__ float g_pooled[(size_t)N_SEG * KDIM];   // [N, 256] = 51.2 MB
__device__ int   g_starts[N_SEG + 1];
__device__ int   g_is64;

// ---------------------------------------------------------------------------
// Kernel -1: detect whether ids are int64 or int32 (odd int32 words all zero
// in the middle of a sorted int64 array with values < 2^31).
// ---------------------------------------------------------------------------
__global__ void detect_kernel(const int* __restrict__ ids32, int M) {
    int base = (M / 2) & ~1;
    int nonzero = 0;
    for (int i = 1; i <= 63; i += 2) {
        if (base + i < M) nonzero |= ids32[base + i];
    }
    g_is64 = (nonzero == 0) ? 1 : 0;
}

// ---------------------------------------------------------------------------
// Kernel 0: segment boundaries from sorted ids (dtype-agnostic via g_is64).
// ---------------------------------------------------------------------------
__global__ void bounds_kernel(const int* __restrict__ ids32, int M, int Nseg) {
    int m = blockIdx.x * blockDim.x + threadIdx.x;
    if (m >= M) return;
    const long long* ids64 = (const long long*)ids32;
    int is64 = g_is64;

    long long id = is64 ? ids64[m] : (long long)ids32[m];
    if (id < 0 || id >= Nseg) return;
    if (m == 0) {
        g_starts[id] = 0;
    } else {
        long long prev = is64 ? ids64[m - 1] : (long long)ids32[m - 1];
        if (prev != id) g_starts[id] = m;
    }
    if (m == M - 1) g_starts[Nseg] = M;
}

// ---------------------------------------------------------------------------
// Kernel 1: segmented max + mean. 4 segments per 128-thread block;
// 32 lanes per segment, each lane owns one float4 (LDG.128, coalesced 512B
// rows). 4-row unroll -> 4 LDG.128 in flight per thread.
// ---------------------------------------------------------------------------
__global__ __launch_bounds__(128) void pool_kernel(const float* __restrict__ lane,
                                                   int M, int Nseg) {
    int group  = threadIdx.x >> 5;     // 0..3
    int lid    = threadIdx.x & 31;     // float4 column
    int seg    = blockIdx.x * 4 + group;
    if (seg >= Nseg) return;

    int s = g_starts[seg];
    int e = g_starts[seg + 1];
    if (s < 0) s = 0;
    if (e > M) e = M;
    int n = e - s;

    float4* dst = (float4*)(g_pooled + (size_t)seg * KDIM);
    if (n <= 0) {
        float4 z = {0.f, 0.f, 0.f, 0.f};
        dst[lid] = z; dst[32 + lid] = z;
        return;
    }

    const float4* p = (const float4*)(lane + (size_t)s * D_FEAT) + lid;
    float ninf = -__int_as_float(0x7f800000);
    float4 mx = {ninf, ninf, ninf, ninf};
    float4 sm = {0.f, 0.f, 0.f, 0.f};

    int r = 0;
    for (; r + 4 <= n; r += 4) {
        float4 a0 = p[(r + 0) * 32];
        float4 a1 = p[(r + 1) * 32];
        float4 a2 = p[(r + 2) * 32];
        float4 a3 = p[(r + 3) * 32];
        mx.x = fmaxf(mx.x, fmaxf(fmaxf(a0.x, a1.x), fmaxf(a2.x, a3.x)));
        mx.y = fmaxf(mx.y, fmaxf(fmaxf(a0.y, a1.y), fmaxf(a2.y, a3.y)));
        mx.z = fmaxf(mx.z, fmaxf(fmaxf(a0.z, a1.z), fmaxf(a2.z, a3.z)));
        mx.w = fmaxf(mx.w, fmaxf(fmaxf(a0.w, a1.w), fmaxf(a2.w, a3.w)));
        sm.x += (a0.x + a1.x) + (a2.x + a3.x);
        sm.y += (a0.y + a1.y) + (a2.y + a3.y);
        sm.z += (a0.z + a1.z) + (a2.z + a3.z);
        sm.w += (a0.w + a1.w) + (a2.w + a3.w);
    }
    for (; r < n; r++) {
        float4 a = p[r * 32];
        mx.x = fmaxf(mx.x, a.x); mx.y = fmaxf(mx.y, a.y);
        mx.z = fmaxf(mx.z, a.z); mx.w = fmaxf(mx.w, a.w);
        sm.x += a.x; sm.y += a.y; sm.z += a.z; sm.w += a.w;
    }

    float inv = 1.f / (float)n;
    float4 mean = {sm.x * inv, sm.y * inv, sm.z * inv, sm.w * inv};
    dst[lid]      = mx;
    dst[32 + lid] = mean;
}

// ---------------------------------------------------------------------------
// Kernel 2: out = relu(pooled @ W^T + b) on the TENSOR pipe.
// Split-tf32 (hi+lo) 3-MMA scheme; hi/lo planes PRE-SPLIT in smem at tile
// fill so the inner loop is pure LDS + MMA (no cvt in the hot path).
// Block: 256 thr (8 warps, 2x4), tile 64x128, K-chunks of 16.
// ---------------------------------------------------------------------------
#define TM 64
#define KC 16
#define KSTRIDE 20   // (20*row + col) % 32 distinct over lr 0..7, lc 0..3

__device__ __forceinline__ void split_tf32(float x, uint32_t& hi, uint32_t& lo) {
    asm("cvt.rna.tf32.f32 %0, %1;" : "=r"(hi) : "f"(x));
    float l = x - __uint_as_float(hi);
    asm("cvt.rna.tf32.f32 %0, %1;" : "=r"(lo) : "f"(l));
}

__device__ __forceinline__ void mma_tf32(float* c, const uint32_t* a, const uint32_t* b) {
    asm volatile(
        "mma.sync.aligned.m16n8k8.row.col.f32.tf32.tf32.f32 "
        "{%0,%1,%2,%3}, {%4,%5,%6,%7}, {%8,%9}, {%0,%1,%2,%3};"
        : "+f"(c[0]), "+f"(c[1]), "+f"(c[2]), "+f"(c[3])
        : "r"(a[0]), "r"(a[1]), "r"(a[2]), "r"(a[3]), "r"(b[0]), "r"(b[1]));
}

__global__ __launch_bounds__(256, 2) void gemm_kernel(const float* __restrict__ W,
                                                      const float* __restrict__ bias,
                                                      float* __restrict__ out,
                                                      int Nrows) {
    __shared__ uint32_t As_hi[TM][KSTRIDE],    As_lo[TM][KSTRIDE];
    __shared__ uint32_t Ws_hi[OUT_F][KSTRIDE], Ws_lo[OUT_F][KSTRIDE];

    int tid  = threadIdx.x;
    int lane = tid & 31;
    int wid  = tid >> 5;
    int warp_m = wid & 1;    // 2 warps in m
    int warp_n = wid >> 1;   // 4 warps in n
    int lr = lane >> 2;      // 0..7
    int lc = lane & 3;       // 0..3
    int row0 = blockIdx.x * TM;

    float acc[2][4][4];
    #pragma unroll
    for (int i = 0; i < 2; i++)
        #pragma unroll
        for (int j = 0; j < 4; j++)
            #pragma unroll
            for (int r = 0; r < 4; r++) acc[i][j][r] = 0.f;

    float ra[4];   // A prefetch: 64*16/256 = 4 per thread
    float rw[8];   // W prefetch: 128*16/256 = 8 per thread

    // Prefetch chunk 0
    #pragma unroll
    for (int i = 0; i < 4; i++) {
        int idx = tid + i * 256;
        int rr = idx >> 4, kk = idx & 15;
        int gr = row0 + rr;
        ra[i] = (gr < Nrows) ? g_pooled[(size_t)gr * KDIM + kk] : 0.f;
    }
    #pragma unroll
    for (int i = 0; i < 8; i++) {
        int idx = tid + i * 256;
        int oo = idx >> 4, kk = idx & 15;
        rw[i] = W[(size_t)oo * KDIM + kk];
    }

    for (int c = 0; c < KDIM / KC; c++) {
        // Split + store to smem planes (conversion happens ONCE per element)
        #pragma unroll
        for (int i = 0; i < 4; i++) {
            int idx = tid + i * 256;
            int rr = idx >> 4, kk = idx & 15;
            uint32_t hi, lo;
            split_tf32(ra[i], hi, lo);
            As_hi[rr][kk] = hi; As_lo[rr][kk] = lo;
        }
        #pragma unroll
        for (int i = 0; i < 8; i++) {
            int idx = tid + i * 256;
            int oo = idx >> 4, kk = idx & 15;
            uint32_t hi, lo;
            split_tf32(rw[i], hi, lo);
            Ws_hi[oo][kk] = hi; Ws_lo[oo][kk] = lo;
        }
        __syncthreads();

        // Prefetch next chunk (overlaps with MMA below)
        if (c + 1 < KDIM / KC) {
            int kc = (c + 1) * KC;
            #pragma unroll
            for (int i = 0; i < 4; i++) {
                int idx = tid + i * 256;
                int rr = idx >> 4, kk = idx & 15;
                int gr = row0 + rr;
                ra[i] = (gr < Nrows) ? g_pooled[(size_t)gr * KDIM + kc + kk] : 0.f;
            }
            #pragma unroll
            for (int i = 0; i < 8; i++) {
                int idx = tid + i * 256;
                int oo = idx >> 4, kk = idx & 15;
                rw[i] = W[(size_t)oo * KDIM + kc + kk];
            }
        }

        // 2 k-atoms of 8 — pure LDS + MMA
        #pragma unroll
        for (int ka = 0; ka < 2; ka++) {
            int k8 = ka * 8;

            uint32_t ah[2][4], al[2][4];
            #pragma unroll
            for (int am = 0; am < 2; am++) {
                int br = warp_m * 32 + am * 16;
                ah[am][0] = As_hi[br + lr    ][k8 + lc    ];
                ah[am][1] = As_hi[br + lr + 8][k8 + lc    ];
                ah[am][2] = As_hi[br + lr    ][k8 + lc + 4];
                ah[am][3] = As_hi[br + lr + 8][k8 + lc + 4];
                al[am][0] = As_lo[br + lr    ][k8 + lc    ];
                al[am][1] = As_lo[br + lr + 8][k8 + lc    ];
                al[am][2] = As_lo[br + lr    ][k8 + lc + 4];
                al[am][3] = As_lo[br + lr + 8][k8 + lc + 4];
            }
            uint32_t bh[4][2], bl[4][2];
            #pragma unroll
            for (int an = 0; an < 4; an++) {
                int bn = warp_n * 32 + an * 8 + lr;
                bh[an][0] = Ws_hi[bn][k8 + lc    ];
                bh[an][1] = Ws_hi[bn][k8 + lc + 4];
                bl[an][0] = Ws_lo[bn][k8 + lc    ];
                bl[an][1] = Ws_lo[bn][k8 + lc + 4];
            }

            #pragma unroll
            for (int am = 0; am < 2; am++)
                #pragma unroll
                for (int an = 0; an < 4; an++) {
                    mma_tf32(acc[am][an], ah[am], bl[an]);  // hi*lo
                    mma_tf32(acc[am][an], al[am], bh[an]);  // lo*hi
                    mma_tf32(acc[am][an], ah[am], bh[an]);  // hi*hi
                }
        }
        __syncthreads();
    }

    // Epilogue: bias + relu
    #pragma unroll
    for (int an = 0; an < 4; an++) {
        int gn = warp_n * 32 + an * 8 + lc * 2;
        float b0 = bias[gn], b1 = bias[gn + 1];
        #pragma unroll
        for (int am = 0; am < 2; am++) {
            int gm0 = row0 + warp_m * 32 + am * 16 + lr;
            int gm1 = gm0 + 8;
            if (gm0 < Nrows) {
                float2 v;
                v.x = fmaxf(acc[am][an][0] + b0, 0.f);
                v.y = fmaxf(acc[am][an][1] + b1, 0.f);
                *(float2*)&out[(size_t)gm0 * OUT_F + gn] = v;
            }
            if (gm1 < Nrows) {
                float2 v;
                v.x = fmaxf(acc[am][an][2] + b0, 0.f);
                v.y = fmaxf(acc[am][an][3] + b1, 0.f);
                *(float2*)&out[(size_t)gm1 * OUT_F + gn] = v;
            }
        }
    }
}

extern "C" void kernel_launch(void* const* d_in, const int* in_sizes, int n_in,
                              void* d_out, int out_size) {
    const float* lane = nullptr;
    const int*   ids  = nullptr;
    const float* W    = nullptr;
    const float* bb   = nullptr;
    int M = 800000, Nseg = 50000;

    for (int i = 0; i < n_in; i++) {
        int sz = in_sizes[i];
        if (sz == 102400000)      lane = (const float*)d_in[i];
        else if (sz == 800000)  { ids  = (const int*)d_in[i]; M = sz; }
        else if (sz == 32768)     W    = (const float*)d_in[i];
        else if (sz == 128)       bb   = (const float*)d_in[i];
        else if (sz == 6400000)   Nseg = sz / D_FEAT;
    }
    if (!lane) lane = (const float*)d_in[1];
    if (!ids)  ids  = (const int*)d_in[2];
    if (!W)    W    = (const float*)d_in[3];
    if (!bb)   bb   = (const float*)d_in[4];

    float* out = (float*)d_out;

    detect_kernel<<<1, 1>>>(ids, M);
    bounds_kernel<<<(M + 255) / 256, 256>>>(ids, M, Nseg);
    pool_kernel<<<(Nseg + 3) / 4, 128>>>(lane, M, Nseg);
    gemm_kernel<<<(Nseg + TM - 1) / TM, 256>>>(W, bb, out, Nseg);
}

// round 7
// speedup vs baseline: 1.4666x; 1.0182x over previous
#include <cuda_runtime.h>
#include <cstdint>

#define N_SEG 50000
#define D_FEAT 128
#define OUT_F 128
#define KDIM 256

// Scratch (allocation-free rule: __device__ globals)
__device__ float g_pooled[(size_t)N_SEG * KDIM];   // [N, 256] = 51.2 MB
__device__ int   g_starts[N_SEG + 1];
__device__ int   g_is64;

// ---------------------------------------------------------------------------
// Kernel -1: detect whether ids are int64 or int32.
// ---------------------------------------------------------------------------
__global__ void detect_kernel(const int* __restrict__ ids32, int M) {
    int base = (M / 2) & ~1;
    int nonzero = 0;
    for (int i = 1; i <= 63; i += 2) {
        if (base + i < M) nonzero |= ids32[base + i];
    }
    g_is64 = (nonzero == 0) ? 1 : 0;
}

// ---------------------------------------------------------------------------
// Kernel 0: segment boundaries from sorted ids.
// ---------------------------------------------------------------------------
__global__ void bounds_kernel(const int* __restrict__ ids32, int M, int Nseg) {
    int m = blockIdx.x * blockDim.x + threadIdx.x;
    if (m >= M) return;
    const long long* ids64 = (const long long*)ids32;
    int is64 = g_is64;

    long long id = is64 ? ids64[m] : (long long)ids32[m];
    if (id < 0 || id >= Nseg) return;
    if (m == 0) {
        g_starts[id] = 0;
    } else {
        long long prev = is64 ? ids64[m - 1] : (long long)ids32[m - 1];
        if (prev != id) g_starts[id] = m;
    }
    if (m == M - 1) g_starts[Nseg] = M;
}

// ---------------------------------------------------------------------------
// Kernel 1: segmented max + mean. 4 segments per 128-thread block;
// 32 lanes per segment, each lane owns one float4 (LDG.128).
// ---------------------------------------------------------------------------
__global__ __launch_bounds__(128) void pool_kernel(const float* __restrict__ lane,
                                                   int M, int Nseg) {
    int group  = threadIdx.x >> 5;
    int lid    = threadIdx.x & 31;
    int seg    = blockIdx.x * 4 + group;
    if (seg >= Nseg) return;

    int s = g_starts[seg];
    int e = g_starts[seg + 1];
    if (s < 0) s = 0;
    if (e > M) e = M;
    int n = e - s;

    float4* dst = (float4*)(g_pooled + (size_t)seg * KDIM);
    if (n <= 0) {
        float4 z = {0.f, 0.f, 0.f, 0.f};
        dst[lid] = z; dst[32 + lid] = z;
        return;
    }

    const float4* p = (const float4*)(lane + (size_t)s * D_FEAT) + lid;
    float ninf = -__int_as_float(0x7f800000);
    float4 mx = {ninf, ninf, ninf, ninf};
    float4 sm = {0.f, 0.f, 0.f, 0.f};

    int r = 0;
    for (; r + 4 <= n; r += 4) {
        float4 a0 = p[(r + 0) * 32];
        float4 a1 = p[(r + 1) * 32];
        float4 a2 = p[(r + 2) * 32];
        float4 a3 = p[(r + 3) * 32];
        mx.x = fmaxf(mx.x, fmaxf(fmaxf(a0.x, a1.x), fmaxf(a2.x, a3.x)));
        mx.y = fmaxf(mx.y, fmaxf(fmaxf(a0.y, a1.y), fmaxf(a2.y, a3.y)));
        mx.z = fmaxf(mx.z, fmaxf(fmaxf(a0.z, a1.z), fmaxf(a2.z, a3.z)));
        mx.w = fmaxf(mx.w, fmaxf(fmaxf(a0.w, a1.w), fmaxf(a2.w, a3.w)));
        sm.x += (a0.x + a1.x) + (a2.x + a3.x);
        sm.y += (a0.y + a1.y) + (a2.y + a3.y);
        sm.z += (a0.z + a1.z) + (a2.z + a3.z);
        sm.w += (a0.w + a1.w) + (a2.w + a3.w);
    }
    for (; r < n; r++) {
        float4 a = p[r * 32];
        mx.x = fmaxf(mx.x, a.x); mx.y = fmaxf(mx.y, a.y);
        mx.z = fmaxf(mx.z, a.z); mx.w = fmaxf(mx.w, a.w);
        sm.x += a.x; sm.y += a.y; sm.z += a.z; sm.w += a.w;
    }

    float inv = 1.f / (float)n;
    float4 mean = {sm.x * inv, sm.y * inv, sm.z * inv, sm.w * inv};
    dst[lid]      = mx;
    dst[32 + lid] = mean;
}

// ---------------------------------------------------------------------------
// Kernel 2: out = relu(pooled @ W^T + b) on the TENSOR pipe.
// Split-tf32 3-MMA; smem holds FRAGMENT-MAJOR hi/lo planes so every
// fragment fetch is one conflict-free LDS.128.
// Block: 256 thr (8 warps, 2x4), tile 64x128, K-chunks of 32.
// ---------------------------------------------------------------------------
#define TM 64
#define KC 32

__device__ __forceinline__ void split_tf32(float x, uint32_t& hi, uint32_t& lo) {
    asm("cvt.rna.tf32.f32 %0, %1;" : "=r"(hi) : "f"(x));
    float l = x - __uint_as_float(hi);
    asm("cvt.rna.tf32.f32 %0, %1;" : "=r"(lo) : "f"(l));
}

__device__ __forceinline__ void mma_tf32_v(float* c, const uint4& a, uint32_t b0, uint32_t b1) {
    asm volatile(
        "mma.sync.aligned.m16n8k8.row.col.f32.tf32.tf32.f32 "
        "{%0,%1,%2,%3}, {%4,%5,%6,%7}, {%8,%9}, {%0,%1,%2,%3};"
        : "+f"(c[0]), "+f"(c[1]), "+f"(c[2]), "+f"(c[3])
        : "r"(a.x), "r"(a.y), "r"(a.z), "r"(a.w), "r"(b0), "r"(b1));
}

__global__ __launch_bounds__(256, 2) void gemm_kernel(const float* __restrict__ W,
                                                      const float* __restrict__ bias,
                                                      float* __restrict__ out,
                                                      int Nrows) {
    // A fragments: [plane hi/lo][ka(4)][m16-tile(4)][lane(32)][reg(4)]  = 16 KB
    // W fragments: [plane][reg(2)][ka(4)][n-group(4)][lane(32)][tile(4)] = 32 KB
    __shared__ __align__(16) uint32_t Af[2][4][4][32][4];
    __shared__ __align__(16) uint32_t Wf[2][2][4][4][32][4];

    int tid  = threadIdx.x;
    int lane = tid & 31;
    int wid  = tid >> 5;
    int warp_m = wid & 1;    // 2 warps in m (m16 tiles warp_m*2 + {0,1})
    int warp_n = wid >> 1;   // 4 warps in n (n-group = warp_n)
    int lr = lane >> 2;
    int lc = lane & 3;
    int row0 = blockIdx.x * TM;

    float acc[2][4][4];
    #pragma unroll
    for (int i = 0; i < 2; i++)
        #pragma unroll
        for (int j = 0; j < 4; j++)
            #pragma unroll
            for (int r = 0; r < 4; r++) acc[i][j][r] = 0.f;

    float ra[8];    // A prefetch: 64*32/256 = 8
    float rw[16];   // W prefetch: 128*32/256 = 16

    // Prefetch chunk 0
    #pragma unroll
    for (int i = 0; i < 8; i++) {
        int idx = tid + i * 256;
        int rr = idx >> 5, kk = idx & 31;
        int gr = row0 + rr;
        ra[i] = (gr < Nrows) ? g_pooled[(size_t)gr * KDIM + kk] : 0.f;
    }
    #pragma unroll
    for (int i = 0; i < 16; i++) {
        int idx = tid + i * 256;
        int oo = idx >> 5, kk = idx & 31;
        rw[i] = W[(size_t)oo * KDIM + kk];
    }

    for (int c = 0; c < KDIM / KC; c++) {
        // Split once per element, store in fragment-major order
        #pragma unroll
        for (int i = 0; i < 8; i++) {
            int idx = tid + i * 256;
            int rr = idx >> 5, kk = idx & 31;
            int ka = kk >> 3, m16 = rr >> 4;
            int fl  = ((rr & 7) << 2) | (kk & 3);
            int reg = ((rr >> 3) & 1) | (((kk >> 2) & 1) << 1);
            uint32_t hi, lo;
            split_tf32(ra[i], hi, lo);
            Af[0][ka][m16][fl][reg] = hi;
            Af[1][ka][m16][fl][reg] = lo;
        }
        #pragma unroll
        for (int i = 0; i < 16; i++) {
            int idx = tid + i * 256;
            int oo = idx >> 5, kk = idx & 31;
            int ka = kk >> 3;
            int n8 = oo >> 3, grp = n8 >> 2, tin = n8 & 3;
            int fl  = ((oo & 7) << 2) | (kk & 3);
            int reg = (kk >> 2) & 1;
            uint32_t hi, lo;
            split_tf32(rw[i], hi, lo);
            Wf[0][reg][ka][grp][fl][tin] = hi;
            Wf[1][reg][ka][grp][fl][tin] = lo;
        }
        __syncthreads();

        // Prefetch next chunk (overlaps with MMA below)
        if (c + 1 < KDIM / KC) {
            int kc = (c + 1) * KC;
            #pragma unroll
            for (int i = 0; i < 8; i++) {
                int idx = tid + i * 256;
                int rr = idx >> 5, kk = idx & 31;
                int gr = row0 + rr;
                ra[i] = (gr < Nrows) ? g_pooled[(size_t)gr * KDIM + kc + kk] : 0.f;
            }
            #pragma unroll
            for (int i = 0; i < 16; i++) {
                int idx = tid + i * 256;
                int oo = idx >> 5, kk = idx & 31;
                rw[i] = W[(size_t)oo * KDIM + kc + kk];
            }
        }

        // 4 k-atoms: all fragment fetches are single conflict-free LDS.128
        #pragma unroll
        for (int ka = 0; ka < 4; ka++) {
            uint4 ah0 = *(const uint4*)Af[0][ka][warp_m * 2 + 0][lane];
            uint4 ah1 = *(const uint4*)Af[0][ka][warp_m * 2 + 1][lane];
            uint4 al0 = *(const uint4*)Af[1][ka][warp_m * 2 + 0][lane];
            uint4 al1 = *(const uint4*)Af[1][ka][warp_m * 2 + 1][lane];
            uint4 bh0 = *(const uint4*)Wf[0][0][ka][warp_n][lane];  // reg0, tiles 0..3
            uint4 bh1 = *(const uint4*)Wf[0][1][ka][warp_n][lane];  // reg1
            uint4 bl0 = *(const uint4*)Wf[1][0][ka][warp_n][lane];
            uint4 bl1 = *(const uint4*)Wf[1][1][ka][warp_n][lane];

            const uint32_t* b0h = &bh0.x;
            const uint32_t* b1h = &bh1.x;
            const uint32_t* b0l = &bl0.x;
            const uint32_t* b1l = &bl1.x;

            #pragma unroll
            for (int an = 0; an < 4; an++) {
                mma_tf32_v(acc[0][an], ah0, b0l[an], b1l[an]);  // hi*lo
                mma_tf32_v(acc[0][an], al0, b0h[an], b1h[an]);  // lo*hi
                mma_tf32_v(acc[0][an], ah0, b0h[an], b1h[an]);  // hi*hi
                mma_tf32_v(acc[1][an], ah1, b0l[an], b1l[an]);
                mma_tf32_v(acc[1][an], al1, b0h[an], b1h[an]);
                mma_tf32_v(acc[1][an], ah1, b0h[an], b1h[an]);
            }
        }
        __syncthreads();
    }

    // Epilogue: bias + relu
    #pragma unroll
    for (int an = 0; an < 4; an++) {
        int gn = warp_n * 32 + an * 8 + lc * 2;
        float b0 = bias[gn], b1 = bias[gn + 1];
        #pragma unroll
        for (int am = 0; am < 2; am++) {
            int gm0 = row0 + warp_m * 32 + am * 16 + lr;
            int gm1 = gm0 + 8;
            if (gm0 < Nrows) {
                float2 v;
                v.x = fmaxf(acc[am][an][0] + b0, 0.f);
                v.y = fmaxf(acc[am][an][1] + b1, 0.f);
                *(float2*)&out[(size_t)gm0 * OUT_F + gn] = v;
            }
            if (gm1 < Nrows) {
                float2 v;
                v.x = fmaxf(acc[am][an][2] + b0, 0.f);
                v.y = fmaxf(acc[am][an][3] + b1, 0.f);
                *(float2*)&out[(size_t)gm1 * OUT_F + gn] = v;
            }
        }
    }
}

extern "C" void kernel_launch(void* const* d_in, const int* in_sizes, int n_in,
                              void* d_out, int out_size) {
    const float* lane = nullptr;
    const int*   ids  = nullptr;
    const float* W    = nullptr;
    const float* bb   = nullptr;
    int M = 800000, Nseg = 50000;

    for (int i = 0; i < n_in; i++) {
        int sz = in_sizes[i];
        if (sz == 102400000)      lane = (const float*)d_in[i];
        else if (sz == 800000)  { ids  = (const int*)d_in[i]; M = sz; }
        else if (sz == 32768)     W    = (const float*)d_in[i];
        else if (sz == 128)       bb   = (const float*)d_in[i];
        else if (sz == 6400000)   Nseg = sz / D_FEAT;
    }
    if (!lane) lane = (const float*)d_in[1];
    if (!ids)  ids  = (const int*)d_in[2];
    if (!W)    W    = (const float*)d_in[3];
    if (!bb)   bb   = (const float*)d_in[4];

    float* out = (float*)d_out;

    detect_kernel<<<1, 1>>>(ids, M);
    bounds_kernel<<<(M + 255) / 256, 256>>>(ids, M, Nseg);
    pool_kernel<<<(Nseg + 3) / 4, 128>>>(lane, M, Nseg);
    gemm_kernel<<<(Nseg + TM - 1) / TM, 256>>>(W, bb, out, Nseg);
}

// round 10
// speedup vs baseline: 1.6816x; 1.1466x over previous
#include <cuda_runtime.h>
#include <cuda_bf16.h>
#include <cstdint>

#define N_SEG 50000
#define D_FEAT 128
#define OUT_F 128
#define KDIM 256
#define KW    (KDIM / 2)   // 128 packed bf16x2 words per row

// Scratch (allocation-free rule: __device__ globals)
__device__ uint32_t g_phi[(size_t)N_SEG * KW];   // pooled hi-plane, packed bf16x2
__device__ uint32_t g_plo[(size_t)N_SEG * KW];   // pooled lo-plane
__device__ uint32_t g_whi[(size_t)OUT_F * KW];   // W hi-plane
__device__ uint32_t g_wlo[(size_t)OUT_F * KW];   // W lo-plane
__device__ int      g_starts[N_SEG + 1];
__device__ int      g_is64;

// Split x into bf16 hi + bf16 lo (x ~= hi + lo), pack pairs along k.
__device__ __forceinline__ void split_pack(float x, float y,
                                           uint32_t& hi, uint32_t& lo) {
    __nv_bfloat162 h2 = __floats2bfloat162_rn(x, y);
    float hx = __bfloat162float(__low2bfloat16(h2));
    float hy = __bfloat162float(__high2bfloat16(h2));
    __nv_bfloat162 l2 = __floats2bfloat162_rn(x - hx, y - hy);
    hi = *(uint32_t*)&h2;
    lo = *(uint32_t*)&l2;
}

// ---------------------------------------------------------------------------
// Kernel -1: detect whether ids are int64 or int32.
// ---------------------------------------------------------------------------
__global__ void detect_kernel(const int* __restrict__ ids32, int M) {
    int base = (M / 2) & ~1;
    int nonzero = 0;
    for (int i = 1; i <= 63; i += 2) {
        if (base + i < M) nonzero |= ids32[base + i];
    }
    g_is64 = (nonzero == 0) ? 1 : 0;
}

// ---------------------------------------------------------------------------
// Kernel 0: segment boundaries from sorted ids.
// ---------------------------------------------------------------------------
__global__ void bounds_kernel(const int* __restrict__ ids32, int M, int Nseg) {
    int m = blockIdx.x * blockDim.x + threadIdx.x;
    if (m >= M) return;
    const long long* ids64 = (const long long*)ids32;
    int is64 = g_is64;

    long long id = is64 ? ids64[m] : (long long)ids32[m];
    if (id < 0 || id >= Nseg) return;
    if (m == 0) {
        g_starts[id] = 0;
    } else {
        long long prev = is64 ? ids64[m - 1] : (long long)ids32[m - 1];
        if (prev != id) g_starts[id] = m;
    }
    if (m == M - 1) g_starts[Nseg] = M;
}

// ---------------------------------------------------------------------------
// Kernel 0b: pre-split W into bf16 hi/lo planes (one-time, tiny).
// ---------------------------------------------------------------------------
__global__ void wsplit_kernel(const float* __restrict__ W) {
    int idx = blockIdx.x * blockDim.x + threadIdx.x;   // word index
    if (idx >= OUT_F * KW) return;
    int oo = idx >> 7;          // row (out feature)
    int kw = idx & (KW - 1);    // packed k-pair
    float x = W[(size_t)oo * KDIM + 2 * kw];
    float y = W[(size_t)oo * KDIM + 2 * kw + 1];
    uint32_t hi, lo;
    split_pack(x, y, hi, lo);
    g_whi[idx] = hi;
    g_wlo[idx] = lo;
}

// ---------------------------------------------------------------------------
// Kernel 1: segmented max + mean -> PRE-SPLIT packed bf16 hi/lo planes.
// 4 segments per 128-thread block; 32 lanes/segment, lane owns one float4.
// ---------------------------------------------------------------------------
__global__ __launch_bounds__(128) void pool_kernel(const float* __restrict__ lane,
                                                   int M, int Nseg) {
    int group  = threadIdx.x >> 5;
    int lid    = threadIdx.x & 31;
    int seg    = blockIdx.x * 4 + group;
    if (seg >= Nseg) return;

    int s = g_starts[seg];
    int e = g_starts[seg + 1];
    if (s < 0) s = 0;
    if (e > M) e = M;
    int n = e - s;

    uint32_t* dhi = g_phi + (size_t)seg * KW;
    uint32_t* dlo = g_plo + (size_t)seg * KW;

    if (n <= 0) {
        dhi[2 * lid] = 0; dhi[2 * lid + 1] = 0;
        dhi[64 + 2 * lid] = 0; dhi[64 + 2 * lid + 1] = 0;
        dlo[2 * lid] = 0; dlo[2 * lid + 1] = 0;
        dlo[64 + 2 * lid] = 0; dlo[64 + 2 * lid + 1] = 0;
        return;
    }

    const float4* p = (const float4*)(lane + (size_t)s * D_FEAT) + lid;
    float ninf = -__int_as_float(0x7f800000);
    float4 mx = {ninf, ninf, ninf, ninf};
    float4 sm = {0.f, 0.f, 0.f, 0.f};

    int r = 0;
    for (; r + 4 <= n; r += 4) {
        float4 a0 = p[(r + 0) * 32];
        float4 a1 = p[(r + 1) * 32];
        float4 a2 = p[(r + 2) * 32];
        float4 a3 = p[(r + 3) * 32];
        mx.x = fmaxf(mx.x, fmaxf(fmaxf(a0.x, a1.x), fmaxf(a2.x, a3.x)));
        mx.y = fmaxf(mx.y, fmaxf(fmaxf(a0.y, a1.y), fmaxf(a2.y, a3.y)));
        mx.z = fmaxf(mx.z, fmaxf(fmaxf(a0.z, a1.z), fmaxf(a2.z, a3.z)));
        mx.w = fmaxf(mx.w, fmaxf(fmaxf(a0.w, a1.w), fmaxf(a2.w, a3.w)));
        sm.x += (a0.x + a1.x) + (a2.x + a3.x);
        sm.y += (a0.y + a1.y) + (a2.y + a3.y);
        sm.z += (a0.z + a1.z) + (a2.z + a3.z);
        sm.w += (a0.w + a1.w) + (a2.w + a3.w);
    }
    for (; r < n; r++) {
        float4 a = p[r * 32];
        mx.x = fmaxf(mx.x, a.x); mx.y = fmaxf(mx.y, a.y);
        mx.z = fmaxf(mx.z, a.z); mx.w = fmaxf(mx.w, a.w);
        sm.x += a.x; sm.y += a.y; sm.z += a.z; sm.w += a.w;
    }

    float inv = 1.f / (float)n;
    uint32_t hi, lo;
    split_pack(mx.x, mx.y, hi, lo);
    dhi[2 * lid] = hi;            dlo[2 * lid] = lo;
    split_pack(mx.z, mx.w, hi, lo);
    dhi[2 * lid + 1] = hi;        dlo[2 * lid + 1] = lo;
    split_pack(sm.x * inv, sm.y * inv, hi, lo);
    dhi[64 + 2 * lid] = hi;       dlo[64 + 2 * lid] = lo;
    split_pack(sm.z * inv, sm.w * inv, hi, lo);
    dhi[64 + 2 * lid + 1] = hi;   dlo[64 + 2 * lid + 1] = lo;
}

// ---------------------------------------------------------------------------
// Kernel 2: out = relu(pooled @ W^T + b), bf16-split 3-MMA (m16n8k16),
// fragment-major smem, everything pre-split. Tile 64x128, KC=32 floats
// (16 packed words) per chunk, 8 warps (2x4).
// ---------------------------------------------------------------------------
#define TM 64

__device__ __forceinline__ void mma_bf16(float* c, const uint4& a,
                                         uint32_t b0, uint32_t b1) {
    asm volatile(
        "mma.sync.aligned.m16n8k16.row.col.f32.bf16.bf16.f32 "
        "{%0,%1,%2,%3}, {%4,%5,%6,%7}, {%8,%9}, {%0,%1,%2,%3};"
        : "+f"(c[0]), "+f"(c[1]), "+f"(c[2]), "+f"(c[3])
        : "r"(a.x), "r"(a.y), "r"(a.z), "r"(a.w), "r"(b0), "r"(b1));
}

__global__ __launch_bounds__(256, 2) void gemm_kernel(const float* __restrict__ bias,
                                                      float* __restrict__ out,
                                                      int Nrows) {
    // A frags: [plane][ka(2)][m16(4)][lane(32)][reg(4)]        = 8 KB
    // W frags: [plane][reg(2)][ka(2)][grp(4)][lane(32)][tile(4)] = 16 KB
    __shared__ __align__(16) uint32_t Af[2][2][4][32][4];
    __shared__ __align__(16) uint32_t Wf[2][2][2][4][32][4];

    int tid  = threadIdx.x;
    int lane = tid & 31;
    int wid  = tid >> 5;
    int warp_m = wid & 1;
    int warp_n = wid >> 1;
    int lr = lane >> 2;
    int lc = lane & 3;
    int row0 = blockIdx.x * TM;

    float acc[2][4][4];
    #pragma unroll
    for (int i = 0; i < 2; i++)
        #pragma unroll
        for (int j = 0; j < 4; j++)
            #pragma unroll
            for (int r = 0; r < 4; r++) acc[i][j][r] = 0.f;

    // Per chunk: 16 packed words per row. A: 64*16*2planes/256 = 8 loads.
    // W: 128*16*2/256 = 16 loads.
    uint32_t ra[8], rw[16];

    // Prefetch chunk 0
    #pragma unroll
    for (int i = 0; i < 4; i++) {
        int idx = tid + i * 256;
        int rr = idx >> 4, kwl = idx & 15;
        int gr = row0 + rr;
        size_t off = (size_t)gr * KW + kwl;
        ra[i]     = (gr < Nrows) ? g_phi[off] : 0u;
        ra[i + 4] = (gr < Nrows) ? g_plo[off] : 0u;
    }
    #pragma unroll
    for (int i = 0; i < 8; i++) {
        int idx = tid + i * 256;
        int oo = idx >> 4, kwl = idx & 15;
        size_t off = (size_t)oo * KW + kwl;
        rw[i]     = g_whi[off];
        rw[i + 8] = g_wlo[off];
    }

    for (int c = 0; c < 8; c++) {     // 8 chunks of 16 packed words
        // Scatter into fragment-major layout
        #pragma unroll
        for (int i = 0; i < 4; i++) {
            int idx = tid + i * 256;
            int rr = idx >> 4, kwl = idx & 15;
            int ka = kwl >> 3, kp = kwl & 7;
            int m16 = rr >> 4, r16 = rr & 15;
            int lt  = ((r16 & 7) << 2) | (kp & 3);
            int reg = ((r16 >> 3) & 1) | ((kp >> 2) << 1);
            Af[0][ka][m16][lt][reg] = ra[i];
            Af[1][ka][m16][lt][reg] = ra[i + 4];
        }
        #pragma unroll
        for (int i = 0; i < 8; i++) {
            int idx = tid + i * 256;
            int oo = idx >> 4, kwl = idx & 15;
            int ka = kwl >> 3, kp = kwl & 7;
            int n8 = oo >> 3, grp = n8 >> 2, tin = n8 & 3;
            int lt  = ((oo & 7) << 2) | (kp & 3);
            int reg = kp >> 2;
            Wf[0][reg][ka][grp][lt][tin] = rw[i];
            Wf[1][reg][ka][grp][lt][tin] = rw[i + 8];
        }
        __syncthreads();

        // Prefetch next chunk (overlaps with MMAs)
        if (c + 1 < 8) {
            int kb = (c + 1) * 16;
            #pragma unroll
            for (int i = 0; i < 4; i++) {
                int idx = tid + i * 256;
                int rr = idx >> 4, kwl = idx & 15;
                int gr = row0 + rr;
                size_t off = (size_t)gr * KW + kb + kwl;
                ra[i]     = (gr < Nrows) ? g_phi[off] : 0u;
                ra[i + 4] = (gr < Nrows) ? g_plo[off] : 0u;
            }
            #pragma unroll
            for (int i = 0; i < 8; i++) {
                int idx = tid + i * 256;
                int oo = idx >> 4, kwl = idx & 15;
                size_t off = (size_t)oo * KW + kb + kwl;
                rw[i]     = g_whi[off];
                rw[i + 8] = g_wlo[off];
            }
        }

        // 2 k16-atoms: fragment fetches are single conflict-free LDS.128
        #pragma unroll
        for (int ka = 0; ka < 2; ka++) {
            uint4 ah0 = *(const uint4*)Af[0][ka][warp_m * 2 + 0][lane];
            uint4 ah1 = *(const uint4*)Af[0][ka][warp_m * 2 + 1][lane];
            uint4 al0 = *(const uint4*)Af[1][ka][warp_m * 2 + 0][lane];
            uint4 al1 = *(const uint4*)Af[1][ka][warp_m * 2 + 1][lane];
            uint4 bh0 = *(const uint4*)Wf[0][0][ka][warp_n][lane];
            uint4 bh1 = *(const uint4*)Wf[0][1][ka][warp_n][lane];
            uint4 bl0 = *(const uint4*)Wf[1][0][ka][warp_n][lane];
            uint4 bl1 = *(const uint4*)Wf[1][1][ka][warp_n][lane];

            const uint32_t* p0h = &bh0.x;
            const uint32_t* p1h = &bh1.x;
            const uint32_t* p0l = &bl0.x;
            const uint32_t* p1l = &bl1.x;

            #pragma unroll
            for (int an = 0; an < 4; an++) {
                mma_bf16(acc[0][an], ah0, p0l[an], p1l[an]);  // hi*lo
                mma_bf16(acc[0][an], al0, p0h[an], p1h[an]);  // lo*hi
                mma_bf16(acc[0][an], ah0, p0h[an], p1h[an]);  // hi*hi
                mma_bf16(acc[1][an], ah1, p0l[an], p1l[an]);
                mma_bf16(acc[1][an], al1, p0h[an], p1h[an]);
                mma_bf16(acc[1][an], ah1, p0h[an], p1h[an]);
            }
        }
        __syncthreads();
    }

    // Epilogue: bias + relu
    #pragma unroll
    for (int an = 0; an < 4; an++) {
        int gn = warp_n * 32 + an * 8 + lc * 2;
        float b0 = bias[gn], b1 = bias[gn + 1];
        #pragma unroll
        for (int am = 0; am < 2; am++) {
            int gm0 = row0 + warp_m * 32 + am * 16 + lr;
            int gm1 = gm0 + 8;
            if (gm0 < Nrows) {
                float2 v;
                v.x = fmaxf(acc[am][an][0] + b0, 0.f);
                v.y = fmaxf(acc[am][an][1] + b1, 0.f);
                *(float2*)&out[(size_t)gm0 * OUT_F + gn] = v;
            }
            if (gm1 < Nrows) {
                float2 v;
                v.x = fmaxf(acc[am][an][2] + b0, 0.f);
                v.y = fmaxf(acc[am][an][3] + b1, 0.f);
                *(float2*)&out[(size_t)gm1 * OUT_F + gn] = v;
            }
        }
    }
}

extern "C" void kernel_launch(void* const* d_in, const int* in_sizes, int n_in,
                              void* d_out, int out_size) {
    const float* lane = nullptr;
    const int*   ids  = nullptr;
    const float* W    = nullptr;
    const float* bb   = nullptr;
    int M = 800000, Nseg = 50000;

    for (int i = 0; i < n_in; i++) {
        int sz = in_sizes[i];
        if (sz == 102400000)      lane = (const float*)d_in[i];
        else if (sz == 800000)  { ids  = (const int*)d_in[i]; M = sz; }
        else if (sz == 32768)     W    = (const float*)d_in[i];
        else if (sz == 128)       bb   = (const float*)d_in[i];
        else if (sz == 6400000)   Nseg = sz / D_FEAT;
    }
    if (!lane) lane = (const float*)d_in[1];
    if (!ids)  ids  = (const int*)d_in[2];
    if (!W)    W    = (const float*)d_in[3];
    if (!bb)   bb   = (const float*)d_in[4];

    float* out = (float*)d_out;

    detect_kernel<<<1, 1>>>(ids, M);
    bounds_kernel<<<(M + 255) / 256, 256>>>(ids, M, Nseg);
    wsplit_kernel<<<(OUT_F * KW + 255) / 256, 256>>>(W);
    pool_kernel<<<(Nseg + 3) / 4, 128>>>(lane, M, Nseg);
    gemm_kernel<<<(Nseg + TM - 1) / TM, 256>>>(bb, out, Nseg);
}